// round 1
// baseline (speedup 1.0000x reference)
#include <cuda_runtime.h>
#include <cuda_bf16.h>
#include <cstdint>

// Problem constants
#define T_TOTAL 512
#define T_STEPS 511     // reference output uses H[-2] = h after step index 510
#define B_SZ    64
#define D_IN    256
#define HID     1024
#define OUT_SZ  256

// Scratch (static __device__ — no allocations allowed)
__device__ float g_P[(size_t)T_STEPS * HID * B_SZ];   // [t][j][b]  ~134 MB
__device__ float g_h[2][HID * B_SZ];                  // [j][b] double buffer

// ---------------- f32x2 packed-FMA helpers (sm_103a FFMA2) ----------------
__device__ __forceinline__ unsigned long long pack2(float a, float b) {
    unsigned long long r;
    asm("mov.b64 %0, {%1, %2};" : "=l"(r) : "f"(a), "f"(b));
    return r;
}
__device__ __forceinline__ float2 unpack2(unsigned long long v) {
    float2 r;
    asm("mov.b64 {%0, %1}, %2;" : "=f"(r.x), "=f"(r.y) : "l"(v));
    return r;
}
__device__ __forceinline__ void ffma2(unsigned long long& acc,
                                      unsigned long long a,
                                      unsigned long long b) {
    asm("fma.rn.f32x2 %0, %1, %2, %0;" : "+l"(acc) : "l"(a), "l"(b));
}

// ---------------- init: zero h0 ----------------
__global__ void zero_h_kernel() {
    int idx = blockIdx.x * blockDim.x + threadIdx.x;     // 16384 threads
    float4 z = make_float4(0.f, 0.f, 0.f, 0.f);
    *(float4*)&g_h[0][idx * 4] = z;
}

// ---------------- precompute: P[t][j][b] = sum_d x[t][b][d]*Wx[d][j] + bias[j] --------
// grid (16 jblocks, 511 t), block 256.  Block tile: 64 j x 64 b, K = 256 in 4 tiles of 64.
// Thread tile: 4 j x 4 b (2 f32x2 pairs per j).
__global__ __launch_bounds__(256) void precompute_kernel(
    const float* __restrict__ x, const float* __restrict__ Wx,
    const float* __restrict__ bias)
{
    __shared__ float xs[64 * 68];   // [d][b], stride 68 (16B-aligned rows, low conflict)
    __shared__ float ws[64 * 64];   // [d][j]

    const int t  = blockIdx.y;
    const int jb = blockIdx.x;          // 16 blocks of 64 j
    const int tid = threadIdx.x;
    const int jt = tid & 15;            // 0..15 -> j local = jt*4
    const int bt = tid >> 4;            // 0..15 -> b local = bt*4

    const float4* x4  = (const float4*)x;   // x[t][b][d], row stride 256 f = 64 f4
    const float4* Wx4 = (const float4*)Wx;  // Wx[d][j],  row stride 1024 f = 256 f4

    unsigned long long acc[4][2];
#pragma unroll
    for (int jj = 0; jj < 4; jj++) { acc[jj][0] = 0ull; acc[jj][1] = 0ull; }

    for (int dt = 0; dt < 4; dt++) {
        // stage x tile (transposed) : xs[d][b]  for d in [dt*64, dt*64+64), all 64 b
#pragma unroll
        for (int i = 0; i < 4; i++) {
            int idx = tid + i * 256;          // 1024 float4 loads
            int b = idx >> 4, q = idx & 15;   // q: which float4 along d
            float4 v = x4[(size_t)t * 4096 + b * 64 + dt * 16 + q];
            int d0 = q * 4;
            xs[(d0 + 0) * 68 + b] = v.x;
            xs[(d0 + 1) * 68 + b] = v.y;
            xs[(d0 + 2) * 68 + b] = v.z;
            xs[(d0 + 3) * 68 + b] = v.w;
        }
        // stage Wx tile : ws[d][j]
#pragma unroll
        for (int i = 0; i < 4; i++) {
            int idx = tid + i * 256;
            int row = idx >> 4, q = idx & 15;
            *(float4*)&ws[row * 64 + q * 4] =
                Wx4[(size_t)(dt * 64 + row) * 256 + jb * 16 + q];
        }
        __syncthreads();

#pragma unroll 8
        for (int dd = 0; dd < 64; dd++) {
            ulonglong2 xv = *(const ulonglong2*)&xs[dd * 68 + bt * 4];
            float4 wv = *(const float4*)&ws[dd * 64 + jt * 4];
            unsigned long long w0 = pack2(wv.x, wv.x);
            unsigned long long w1 = pack2(wv.y, wv.y);
            unsigned long long w2 = pack2(wv.z, wv.z);
            unsigned long long w3 = pack2(wv.w, wv.w);
            ffma2(acc[0][0], xv.x, w0); ffma2(acc[0][1], xv.y, w0);
            ffma2(acc[1][0], xv.x, w1); ffma2(acc[1][1], xv.y, w1);
            ffma2(acc[2][0], xv.x, w2); ffma2(acc[2][1], xv.y, w2);
            ffma2(acc[3][0], xv.x, w3); ffma2(acc[3][1], xv.y, w3);
        }
        __syncthreads();
    }

    // epilogue: add bias, store P[t][j][b0..b0+3]
    const int b0 = bt * 4;
#pragma unroll
    for (int jj = 0; jj < 4; jj++) {
        int j = jb * 64 + jt * 4 + jj;
        float bj = bias[j];
        float2 a0 = unpack2(acc[jj][0]);
        float2 a1 = unpack2(acc[jj][1]);
        float4 o = make_float4(a0.x + bj, a0.y + bj, a1.x + bj, a1.y + bj);
        *(float4*)&g_P[((size_t)t * HID + j) * B_SZ + b0] = o;
    }
}

// ---------------- recurrence step: h_new[j][b] = tanh(P[t][j][b] + sum_k h[k][b]*Wh[k][j]) ----
// grid (32 jblocks, 4 bblocks), block 128.  CTA tile: 32 j x 16 b, K = 1024 in 8 chunks of 128.
// Thread tile: 1 j x 4 b (2 f32x2 accumulators). Smem ping-pong + register prefetch.
__global__ __launch_bounds__(128) void step_kernel(const float* __restrict__ Wh, int t)
{
    __shared__ float hs[2][128 * 16];   // [kk][b] 16B rows
    __shared__ float ws[2][128 * 32];   // [kk][j]

    const int tid = threadIdx.x;
    const int jl = tid & 31;            // local j = lane
    const int bt = tid >> 5;            // 0..3 -> local b = bt*4
    const int jb = blockIdx.x;          // 32 blocks of 32 j
    const int bb = blockIdx.y;          // 4 blocks of 16 b

    const float* hprev = g_h[t & 1];
    float*       hnext = g_h[(t + 1) & 1];

    const float4* hp4 = (const float4*)hprev;   // h[k][b], row = 16 f4
    const float4* wh4 = (const float4*)Wh;      // Wh[k][j], row = 256 f4

    float4 hreg[4], wreg[8];

    // prefetch chunk 0
#pragma unroll
    for (int i = 0; i < 4; i++) {
        int idx = tid + i * 128; int row = idx >> 2, q = idx & 3;
        hreg[i] = hp4[(size_t)row * 16 + bb * 4 + q];
    }
#pragma unroll
    for (int i = 0; i < 8; i++) {
        int idx = tid + i * 128; int row = idx >> 3, q = idx & 7;
        wreg[i] = wh4[(size_t)row * 256 + jb * 8 + q];
    }
    // store chunk 0 to buf 0
#pragma unroll
    for (int i = 0; i < 4; i++) {
        int idx = tid + i * 128; int row = idx >> 2, q = idx & 3;
        *(float4*)&hs[0][row * 16 + q * 4] = hreg[i];
    }
#pragma unroll
    for (int i = 0; i < 8; i++) {
        int idx = tid + i * 128; int row = idx >> 3, q = idx & 7;
        *(float4*)&ws[0][row * 32 + q * 4] = wreg[i];
    }
    __syncthreads();

    unsigned long long acc0 = 0ull, acc1 = 0ull;

    for (int c = 0; c < 8; c++) {
        const int s = c & 1;
        // prefetch next chunk into registers (overlaps with compute below)
        if (c < 7) {
            const int k0 = (c + 1) * 128;
#pragma unroll
            for (int i = 0; i < 4; i++) {
                int idx = tid + i * 128; int row = idx >> 2, q = idx & 3;
                hreg[i] = hp4[(size_t)(k0 + row) * 16 + bb * 4 + q];
            }
#pragma unroll
            for (int i = 0; i < 8; i++) {
                int idx = tid + i * 128; int row = idx >> 3, q = idx & 7;
                wreg[i] = wh4[(size_t)(k0 + row) * 256 + jb * 8 + q];
            }
        }
        // compute current chunk from smem
#pragma unroll 8
        for (int kk = 0; kk < 128; kk++) {
            ulonglong2 hv = *(const ulonglong2*)&hs[s][kk * 16 + bt * 4];
            float w = ws[s][kk * 32 + jl];
            unsigned long long wp = pack2(w, w);
            ffma2(acc0, hv.x, wp);
            ffma2(acc1, hv.y, wp);
        }
        __syncthreads();
        if (c < 7) {
            const int d = s ^ 1;
#pragma unroll
            for (int i = 0; i < 4; i++) {
                int idx = tid + i * 128; int row = idx >> 2, q = idx & 3;
                *(float4*)&hs[d][row * 16 + q * 4] = hreg[i];
            }
#pragma unroll
            for (int i = 0; i < 8; i++) {
                int idx = tid + i * 128; int row = idx >> 3, q = idx & 7;
                *(float4*)&ws[d][row * 32 + q * 4] = wreg[i];
            }
            __syncthreads();
        }
    }

    // epilogue: + P, tanh, write h_new
    const int j = jb * 32 + jl;
    const int b0 = bb * 16 + bt * 4;
    float4 pv = *(const float4*)&g_P[((size_t)t * HID + j) * B_SZ + b0];
    float2 a0 = unpack2(acc0), a1 = unpack2(acc1);
    float4 o;
    o.x = tanhf(pv.x + a0.x);
    o.y = tanhf(pv.y + a0.y);
    o.z = tanhf(pv.z + a1.x);
    o.w = tanhf(pv.w + a1.y);
    *(float4*)&hnext[j * B_SZ + b0] = o;
}

// ---------------- final: y[b][o] = sum_j h[j][b]*W2[j][o] + b2[o] ----------------
// grid (8 oblocks, 4 bblocks), block 128.  CTA tile: 32 o x 16 b, K = 1024.
__global__ __launch_bounds__(128) void final_kernel(
    const float* __restrict__ W2, const float* __restrict__ b2,
    float* __restrict__ out)
{
    __shared__ float hs[128 * 16];
    __shared__ float ws[128 * 32];

    const int tid = threadIdx.x;
    const int ol = tid & 31;
    const int bt = tid >> 5;
    const int ob = blockIdx.x;          // 8 blocks of 32 o
    const int bb = blockIdx.y;          // 4 blocks of 16 b

    const float* hfin = g_h[T_STEPS & 1];       // g_h[1]
    const float4* hp4 = (const float4*)hfin;
    const float4* w24 = (const float4*)W2;      // W2[j][o], row = 64 f4

    unsigned long long acc0 = 0ull, acc1 = 0ull;

    for (int c = 0; c < 8; c++) {
        const int k0 = c * 128;
#pragma unroll
        for (int i = 0; i < 4; i++) {
            int idx = tid + i * 128; int row = idx >> 2, q = idx & 3;
            *(float4*)&hs[row * 16 + q * 4] = hp4[(size_t)(k0 + row) * 16 + bb * 4 + q];
        }
#pragma unroll
        for (int i = 0; i < 8; i++) {
            int idx = tid + i * 128; int row = idx >> 3, q = idx & 7;
            *(float4*)&ws[row * 32 + q * 4] = w24[(size_t)(k0 + row) * 64 + ob * 8 + q];
        }
        __syncthreads();
#pragma unroll 8
        for (int kk = 0; kk < 128; kk++) {
            ulonglong2 hv = *(const ulonglong2*)&hs[kk * 16 + bt * 4];
            float w = ws[kk * 32 + ol];
            unsigned long long wp = pack2(w, w);
            ffma2(acc0, hv.x, wp);
            ffma2(acc1, hv.y, wp);
        }
        __syncthreads();
    }

    const int o = ob * 32 + ol;
    const int b0 = bb * 16 + bt * 4;
    const float bo = b2[o];
    float2 a0 = unpack2(acc0), a1 = unpack2(acc1);
    out[(b0 + 0) * OUT_SZ + o] = a0.x + bo;
    out[(b0 + 1) * OUT_SZ + o] = a0.y + bo;
    out[(b0 + 2) * OUT_SZ + o] = a1.x + bo;
    out[(b0 + 3) * OUT_SZ + o] = a1.y + bo;
}

// ---------------- launch ----------------
extern "C" void kernel_launch(void* const* d_in, const int* in_sizes, int n_in,
                              void* d_out, int out_size)
{
    const float* x   = (const float*)d_in[0];
    const float* Wx  = (const float*)d_in[1];
    const float* Wh  = (const float*)d_in[2];
    const float* b   = (const float*)d_in[3];
    const float* W2  = (const float*)d_in[4];
    const float* b2  = (const float*)d_in[5];
    float* out = (float*)d_out;

    zero_h_kernel<<<64, 256>>>();
    precompute_kernel<<<dim3(16, T_STEPS), 256>>>(x, Wx, b);
    for (int t = 0; t < T_STEPS; t++) {
        step_kernel<<<dim3(32, 4), 128>>>(Wh, t);
    }
    final_kernel<<<dim3(8, 4), 128>>>(W2, b2, out);
}

// round 2
// speedup vs baseline: 1.4985x; 1.4985x over previous
#include <cuda_runtime.h>
#include <cuda_bf16.h>
#include <cstdint>

// Problem constants
#define T_TOTAL 512
#define T_STEPS 511     // reference output uses H[-2] = h after step index 510
#define B_SZ    64
#define D_IN    256
#define HID     1024
#define OUT_SZ  256

// Scratch (static __device__ — no allocations allowed)
__device__ float g_P[(size_t)T_STEPS * HID * B_SZ];   // [t][j][b]  ~134 MB
__device__ float g_h[2][HID * B_SZ];                  // [j][b] double buffer

// ---------------- f32x2 packed-FMA helpers (sm_103a FFMA2) ----------------
__device__ __forceinline__ unsigned long long pack2(float a, float b) {
    unsigned long long r;
    asm("mov.b64 %0, {%1, %2};" : "=l"(r) : "f"(a), "f"(b));
    return r;
}
__device__ __forceinline__ float2 unpack2(unsigned long long v) {
    float2 r;
    asm("mov.b64 {%0, %1}, %2;" : "=f"(r.x), "=f"(r.y) : "l"(v));
    return r;
}
__device__ __forceinline__ void ffma2(unsigned long long& acc,
                                      unsigned long long a,
                                      unsigned long long b) {
    asm("fma.rn.f32x2 %0, %1, %2, %0;" : "+l"(acc) : "l"(a), "l"(b));
}

// ---------------- init: zero h0 ----------------
__global__ void zero_h_kernel() {
    int idx = blockIdx.x * blockDim.x + threadIdx.x;     // 16384 threads
    float4 z = make_float4(0.f, 0.f, 0.f, 0.f);
    *(float4*)&g_h[0][idx * 4] = z;
}

// ---------------- precompute: P[t][j][b] = sum_d x[t][b][d]*Wx[d][j] + bias[j] --------
// (near fp32 roofline already; unchanged from round 1)
__global__ __launch_bounds__(256) void precompute_kernel(
    const float* __restrict__ x, const float* __restrict__ Wx,
    const float* __restrict__ bias)
{
    __shared__ float xs[64 * 68];
    __shared__ float ws[64 * 64];

    const int t  = blockIdx.y;
    const int jb = blockIdx.x;
    const int tid = threadIdx.x;
    const int jt = tid & 15;
    const int bt = tid >> 4;

    const float4* x4  = (const float4*)x;
    const float4* Wx4 = (const float4*)Wx;

    unsigned long long acc[4][2];
#pragma unroll
    for (int jj = 0; jj < 4; jj++) { acc[jj][0] = 0ull; acc[jj][1] = 0ull; }

    for (int dt = 0; dt < 4; dt++) {
#pragma unroll
        for (int i = 0; i < 4; i++) {
            int idx = tid + i * 256;
            int b = idx >> 4, q = idx & 15;
            float4 v = x4[(size_t)t * 4096 + b * 64 + dt * 16 + q];
            int d0 = q * 4;
            xs[(d0 + 0) * 68 + b] = v.x;
            xs[(d0 + 1) * 68 + b] = v.y;
            xs[(d0 + 2) * 68 + b] = v.z;
            xs[(d0 + 3) * 68 + b] = v.w;
        }
#pragma unroll
        for (int i = 0; i < 4; i++) {
            int idx = tid + i * 256;
            int row = idx >> 4, q = idx & 15;
            *(float4*)&ws[row * 64 + q * 4] =
                Wx4[(size_t)(dt * 64 + row) * 256 + jb * 16 + q];
        }
        __syncthreads();

#pragma unroll 8
        for (int dd = 0; dd < 64; dd++) {
            ulonglong2 xv = *(const ulonglong2*)&xs[dd * 68 + bt * 4];
            float4 wv = *(const float4*)&ws[dd * 64 + jt * 4];
            unsigned long long w0 = pack2(wv.x, wv.x);
            unsigned long long w1 = pack2(wv.y, wv.y);
            unsigned long long w2 = pack2(wv.z, wv.z);
            unsigned long long w3 = pack2(wv.w, wv.w);
            ffma2(acc[0][0], xv.x, w0); ffma2(acc[0][1], xv.y, w0);
            ffma2(acc[1][0], xv.x, w1); ffma2(acc[1][1], xv.y, w1);
            ffma2(acc[2][0], xv.x, w2); ffma2(acc[2][1], xv.y, w2);
            ffma2(acc[3][0], xv.x, w3); ffma2(acc[3][1], xv.y, w3);
        }
        __syncthreads();
    }

    const int b0 = bt * 4;
#pragma unroll
    for (int jj = 0; jj < 4; jj++) {
        int j = jb * 64 + jt * 4 + jj;
        float bj = bias[j];
        float2 a0 = unpack2(acc[jj][0]);
        float2 a1 = unpack2(acc[jj][1]);
        float4 o = make_float4(a0.x + bj, a0.y + bj, a1.x + bj, a1.y + bj);
        *(float4*)&g_P[((size_t)t * HID + j) * B_SZ + b0] = o;
    }
}

// ---------------- recurrence step v2 ----------------
// h_new[j][b] = tanh(P[t][j][b] + sum_k h[k][b]*Wh[k][j])
// grid (32 jb, 4 bb) = 128 CTAs, 512 threads = 16 warps.
// Warp w owns k in [w*64, w*64+64), covers the FULL 32j x 16b tile.
// Thread tile 2j x 8b -> 8 f32x2 accumulators (61% fma density).
// Per-warp smem staging in 16-k sub-chunks; warp-synchronous mainloop
// (no __syncthreads until the final cross-warp reduction).
__global__ __launch_bounds__(512) void step_kernel(const float* __restrict__ Wh, int t)
{
    __shared__ float hs[16][16 * 16];   // [warp][k16 x b16]  16 KB
    __shared__ float ws[16][16 * 32];   // [warp][k16 x j32]  32 KB (reused for reduction)

    const int tid = threadIdx.x;
    const int w   = tid >> 5;
    const int l   = tid & 31;
    const int jp  = l & 15;            // j pair index: j_local = jp*2 + {0,1}
    const int bh  = l >> 4;            // b half: b_local = bh*8 + {0..7}
    const int jb  = blockIdx.x;        // 32 blocks of 32 j
    const int bb  = blockIdx.y;        // 4 blocks of 16 b

    const float* hprev = g_h[t & 1];
    float*       hnext = g_h[(t + 1) & 1];

    const float4* hp4 = (const float4*)hprev;   // h[k][b],  row = 16 f4
    const float4* wh4 = (const float4*)Wh;      // Wh[k][j], row = 256 f4

    // staging index math (per lane)
    // h sub-chunk: 16k x 16b = 64 f4, lane loads idx = l, l+32
    const int h_kk0 = l >> 2,        h_q0 = l & 3;
    const int h_kk1 = (l + 32) >> 2, h_q1 = (l + 32) & 3;
    // w sub-chunk: 16k x 32j = 128 f4, lane loads idx = l + 32*i, i=0..3
    // kk = idx>>3, q = idx&7

    unsigned long long acc[2][4];
#pragma unroll
    for (int jj = 0; jj < 2; jj++)
#pragma unroll
        for (int p = 0; p < 4; p++) acc[jj][p] = 0ull;

    const int k0w = w * 64;

    float4 hreg[2], wreg[4];

    // prefetch sub-chunk 0
    {
        const int k0 = k0w;
        hreg[0] = hp4[(size_t)(k0 + h_kk0) * 16 + bb * 4 + h_q0];
        hreg[1] = hp4[(size_t)(k0 + h_kk1) * 16 + bb * 4 + h_q1];
#pragma unroll
        for (int i = 0; i < 4; i++) {
            int idx = l + 32 * i; int kk = idx >> 3, q = idx & 7;
            wreg[i] = wh4[(size_t)(k0 + kk) * 256 + jb * 8 + q];
        }
    }

#pragma unroll
    for (int sc = 0; sc < 4; sc++) {
        // store staged regs -> smem
        *(float4*)&hs[w][h_kk0 * 16 + h_q0 * 4] = hreg[0];
        *(float4*)&hs[w][h_kk1 * 16 + h_q1 * 4] = hreg[1];
#pragma unroll
        for (int i = 0; i < 4; i++) {
            int idx = l + 32 * i; int kk = idx >> 3, q = idx & 7;
            *(float4*)&ws[w][kk * 32 + q * 4] = wreg[i];
        }
        __syncwarp();

        // prefetch next sub-chunk (overlaps with compute)
        if (sc < 3) {
            const int k0 = k0w + (sc + 1) * 16;
            hreg[0] = hp4[(size_t)(k0 + h_kk0) * 16 + bb * 4 + h_q0];
            hreg[1] = hp4[(size_t)(k0 + h_kk1) * 16 + bb * 4 + h_q1];
#pragma unroll
            for (int i = 0; i < 4; i++) {
                int idx = l + 32 * i; int kk = idx >> 3, q = idx & 7;
                wreg[i] = wh4[(size_t)(k0 + kk) * 256 + jb * 8 + q];
            }
        }

        // compute 16 k from smem: per k, 13 instrs of which 8 FFMA2
#pragma unroll
        for (int kk = 0; kk < 16; kk++) {
            ulonglong2 hv01 = *(const ulonglong2*)&hs[w][kk * 16 + bh * 8];
            ulonglong2 hv23 = *(const ulonglong2*)&hs[w][kk * 16 + bh * 8 + 4];
            float2 wp = *(const float2*)&ws[w][kk * 32 + jp * 2];
            unsigned long long w0 = pack2(wp.x, wp.x);
            unsigned long long w1 = pack2(wp.y, wp.y);
            ffma2(acc[0][0], hv01.x, w0);
            ffma2(acc[0][1], hv01.y, w0);
            ffma2(acc[0][2], hv23.x, w0);
            ffma2(acc[0][3], hv23.y, w0);
            ffma2(acc[1][0], hv01.x, w1);
            ffma2(acc[1][1], hv01.y, w1);
            ffma2(acc[1][2], hv23.x, w1);
            ffma2(acc[1][3], hv23.y, w1);
        }
        __syncwarp();
    }

    // cross-warp reduction: 16 partial tiles -> 1
    __syncthreads();
    // reuse ws as red[warp][512]: output o = j_local*16 + b_local
#pragma unroll
    for (int jj = 0; jj < 2; jj++) {
        int o = (jp * 2 + jj) * 16 + bh * 8;
        *(float4*)&ws[w][o]     = make_float4(unpack2(acc[jj][0]).x, unpack2(acc[jj][0]).y,
                                              unpack2(acc[jj][1]).x, unpack2(acc[jj][1]).y);
        *(float4*)&ws[w][o + 4] = make_float4(unpack2(acc[jj][2]).x, unpack2(acc[jj][2]).y,
                                              unpack2(acc[jj][3]).x, unpack2(acc[jj][3]).y);
    }
    __syncthreads();

    // each thread finalizes one output: o = tid
    {
        const int o  = tid;
        const int jl = o >> 4;
        const int bl = o & 15;
        float s = 0.f;
#pragma unroll
        for (int ww = 0; ww < 16; ww++) s += ws[ww][o];
        const int j = jb * 32 + jl;
        const int b = bb * 16 + bl;
        float p = g_P[((size_t)t * HID + j) * B_SZ + b];
        hnext[j * B_SZ + b] = tanhf(p + s);
    }
}

// ---------------- final: y[b][o] = sum_j h[j][b]*W2[j][o] + b2[o] ----------------
__global__ __launch_bounds__(128) void final_kernel(
    const float* __restrict__ W2, const float* __restrict__ b2,
    float* __restrict__ out)
{
    __shared__ float hs[128 * 16];
    __shared__ float ws[128 * 32];

    const int tid = threadIdx.x;
    const int ol = tid & 31;
    const int bt = tid >> 5;
    const int ob = blockIdx.x;
    const int bb = blockIdx.y;

    const float* hfin = g_h[T_STEPS & 1];
    const float4* hp4 = (const float4*)hfin;
    const float4* w24 = (const float4*)W2;

    unsigned long long acc0 = 0ull, acc1 = 0ull;

    for (int c = 0; c < 8; c++) {
        const int k0 = c * 128;
#pragma unroll
        for (int i = 0; i < 4; i++) {
            int idx = tid + i * 128; int row = idx >> 2, q = idx & 3;
            *(float4*)&hs[row * 16 + q * 4] = hp4[(size_t)(k0 + row) * 16 + bb * 4 + q];
        }
#pragma unroll
        for (int i = 0; i < 8; i++) {
            int idx = tid + i * 128; int row = idx >> 3, q = idx & 7;
            *(float4*)&ws[row * 32 + q * 4] = w24[(size_t)(k0 + row) * 64 + ob * 8 + q];
        }
        __syncthreads();
#pragma unroll 8
        for (int kk = 0; kk < 128; kk++) {
            ulonglong2 hv = *(const ulonglong2*)&hs[kk * 16 + bt * 4];
            float w = ws[kk * 32 + ol];
            unsigned long long wp = pack2(w, w);
            ffma2(acc0, hv.x, wp);
            ffma2(acc1, hv.y, wp);
        }
        __syncthreads();
    }

    const int o = ob * 32 + ol;
    const int b0 = bb * 16 + bt * 4;
    const float bo = b2[o];
    float2 a0 = unpack2(acc0), a1 = unpack2(acc1);
    out[(b0 + 0) * OUT_SZ + o] = a0.x + bo;
    out[(b0 + 1) * OUT_SZ + o] = a0.y + bo;
    out[(b0 + 2) * OUT_SZ + o] = a1.x + bo;
    out[(b0 + 3) * OUT_SZ + o] = a1.y + bo;
}

// ---------------- launch ----------------
extern "C" void kernel_launch(void* const* d_in, const int* in_sizes, int n_in,
                              void* d_out, int out_size)
{
    const float* x   = (const float*)d_in[0];
    const float* Wx  = (const float*)d_in[1];
    const float* Wh  = (const float*)d_in[2];
    const float* b   = (const float*)d_in[3];
    const float* W2  = (const float*)d_in[4];
    const float* b2  = (const float*)d_in[5];
    float* out = (float*)d_out;

    zero_h_kernel<<<64, 256>>>();
    precompute_kernel<<<dim3(16, T_STEPS), 256>>>(x, Wx, b);
    for (int t = 0; t < T_STEPS; t++) {
        step_kernel<<<dim3(32, 4), 512>>>(Wh, t);
    }
    final_kernel<<<dim3(8, 4), 128>>>(W2, b2, out);
}

// round 3
// speedup vs baseline: 1.6457x; 1.0982x over previous
#include <cuda_runtime.h>
#include <cuda_bf16.h>
#include <cstdint>

// Problem constants
#define T_TOTAL 512
#define T_STEPS 511     // reference output uses H[-2] = h after step index 510
#define B_SZ    64
#define D_IN    256
#define HID     1024
#define OUT_SZ  256
#define NCTA    128     // persistent grid: 32 jb x 4 bb  (<= 148 SMs -> all resident)

// Scratch (static __device__ — no allocations allowed)
__device__ float g_P[(size_t)T_STEPS * HID * B_SZ];   // [t][j][b]  ~134 MB
__device__ float g_h[2][HID * B_SZ];                  // [j][b] double buffer

// software grid barrier state (zero-init; stays consistent across graph replays)
__device__ unsigned long long g_bar_arrive;
__device__ unsigned long long g_bar_gen;

// ---------------- f32x2 packed-FMA helpers (sm_103a FFMA2) ----------------
__device__ __forceinline__ unsigned long long pack2(float a, float b) {
    unsigned long long r;
    asm("mov.b64 %0, {%1, %2};" : "=l"(r) : "f"(a), "f"(b));
    return r;
}
__device__ __forceinline__ float2 unpack2(unsigned long long v) {
    float2 r;
    asm("mov.b64 {%0, %1}, %2;" : "=f"(r.x), "=f"(r.y) : "l"(v));
    return r;
}
__device__ __forceinline__ void ffma2(unsigned long long& acc,
                                      unsigned long long a,
                                      unsigned long long b) {
    asm("fma.rn.f32x2 %0, %1, %2, %0;" : "+l"(acc) : "l"(a), "l"(b));
}
// L1-bypassing vector load (cross-SM coherent at L2) for the h ring buffer
__device__ __forceinline__ float4 ldcg4(const float4* p) {
    float4 v;
    asm volatile("ld.global.cg.v4.f32 {%0,%1,%2,%3}, [%4];"
                 : "=f"(v.x), "=f"(v.y), "=f"(v.z), "=f"(v.w) : "l"(p));
    return v;
}

// ---------------- precompute: P[t][j][b] = sum_d x[t][b][d]*Wx[d][j] + bias[j] --------
__global__ __launch_bounds__(256) void precompute_kernel(
    const float* __restrict__ x, const float* __restrict__ Wx,
    const float* __restrict__ bias)
{
    __shared__ float xs[64 * 68];
    __shared__ float ws[64 * 64];

    const int t  = blockIdx.y;
    const int jb = blockIdx.x;
    const int tid = threadIdx.x;
    const int jt = tid & 15;
    const int bt = tid >> 4;

    const float4* x4  = (const float4*)x;
    const float4* Wx4 = (const float4*)Wx;

    unsigned long long acc[4][2];
#pragma unroll
    for (int jj = 0; jj < 4; jj++) { acc[jj][0] = 0ull; acc[jj][1] = 0ull; }

    for (int dt = 0; dt < 4; dt++) {
#pragma unroll
        for (int i = 0; i < 4; i++) {
            int idx = tid + i * 256;
            int b = idx >> 4, q = idx & 15;
            float4 v = x4[(size_t)t * 4096 + b * 64 + dt * 16 + q];
            int d0 = q * 4;
            xs[(d0 + 0) * 68 + b] = v.x;
            xs[(d0 + 1) * 68 + b] = v.y;
            xs[(d0 + 2) * 68 + b] = v.z;
            xs[(d0 + 3) * 68 + b] = v.w;
        }
#pragma unroll
        for (int i = 0; i < 4; i++) {
            int idx = tid + i * 256;
            int row = idx >> 4, q = idx & 15;
            *(float4*)&ws[row * 64 + q * 4] =
                Wx4[(size_t)(dt * 64 + row) * 256 + jb * 16 + q];
        }
        __syncthreads();

#pragma unroll 8
        for (int dd = 0; dd < 64; dd++) {
            ulonglong2 xv = *(const ulonglong2*)&xs[dd * 68 + bt * 4];
            float4 wv = *(const float4*)&ws[dd * 64 + jt * 4];
            unsigned long long w0 = pack2(wv.x, wv.x);
            unsigned long long w1 = pack2(wv.y, wv.y);
            unsigned long long w2 = pack2(wv.z, wv.z);
            unsigned long long w3 = pack2(wv.w, wv.w);
            ffma2(acc[0][0], xv.x, w0); ffma2(acc[0][1], xv.y, w0);
            ffma2(acc[1][0], xv.x, w1); ffma2(acc[1][1], xv.y, w1);
            ffma2(acc[2][0], xv.x, w2); ffma2(acc[2][1], xv.y, w2);
            ffma2(acc[3][0], xv.x, w3); ffma2(acc[3][1], xv.y, w3);
        }
        __syncthreads();
    }

    const int b0 = bt * 4;
#pragma unroll
    for (int jj = 0; jj < 4; jj++) {
        int j = jb * 64 + jt * 4 + jj;
        float bj = bias[j];
        float2 a0 = unpack2(acc[jj][0]);
        float2 a1 = unpack2(acc[jj][1]);
        float4 o = make_float4(a0.x + bj, a0.y + bj, a1.x + bj, a1.y + bj);
        *(float4*)&g_P[((size_t)t * HID + j) * B_SZ + b0] = o;
    }
}

// ---------------- persistent recurrence kernel ----------------
// grid (32 jb, 4 bb) = 128 CTAs, 512 threads = 16 warps. All CTAs resident.
// Wh slice [1024 k][32 j] lives in smem for the whole kernel (128 KB).
// Per step: warp w reduces k in [w*64, w*64+64) over the 32j x 16b tile
// (thread tile 2j x 8b -> 8 f32x2 accumulators); h streamed via ld.cg into
// a per-warp smem ping-pong; cross-warp k-reduction; tanh; grid barrier.
__device__ __forceinline__ void grid_barrier() {
    __threadfence();
    __syncthreads();
    if (threadIdx.x == 0) {
        unsigned long long arr = atomicAdd(&g_bar_arrive, 1ULL);
        unsigned long long target = arr / NCTA + 1;
        if ((arr % NCTA) == (NCTA - 1)) {
            atomicAdd(&g_bar_gen, 1ULL);       // release this generation
        } else {
            while (*(volatile unsigned long long*)&g_bar_gen < target) { }
            __threadfence();                    // acquire
        }
    }
    __syncthreads();
}

__global__ __launch_bounds__(512) void rnn_persistent_kernel(const float* __restrict__ Wh)
{
    extern __shared__ float smem[];
    float* whs    = smem;            // [1024 k][32 j]            = 32768 floats (128 KB)
    float* hstage = smem + 32768;    // [16 warp][2 buf][16k*16b] =  8192 floats (32 KB)
                                     // (reused as red[16][512] for the k-reduction)

    const int tid = threadIdx.x;
    const int w   = tid >> 5;
    const int l   = tid & 31;
    const int jp  = l & 15;            // j pair: j_local = jp*2 + {0,1}
    const int bh  = l >> 4;            // b half: b_local = bh*8 + {0..7}
    const int jb  = blockIdx.x;        // 32 blocks of 32 j
    const int bb  = blockIdx.y;        // 4 blocks of 16 b

    // ---- load Wh slice into smem once: whs[k*32 + jl] ----
    {
        const float4* wh4  = (const float4*)Wh;    // Wh[k][j], row = 256 f4
        float4*       whs4 = (float4*)whs;         // row = 8 f4
#pragma unroll
        for (int i = 0; i < 16; i++) {
            int idx = tid + i * 512;               // 8192 float4
            int k = idx >> 3, q = idx & 7;
            whs4[k * 8 + q] = wh4[(size_t)k * 256 + jb * 8 + q];
        }
    }

    // ---- zero h0 slice (this CTA owns j in [jb*32,..), b in [bb*16,..)) ----
    {
        int jl = tid >> 4, bl = tid & 15;
        g_h[0][(jb * 32 + jl) * B_SZ + bb * 16 + bl] = 0.f;
    }
    grid_barrier();   // zeros visible everywhere (also covers the smem Wh via syncthreads)

    const int k0w = w * 64;
    float* hst = hstage + w * 512;     // 2 buffers x 256 floats

    // per-lane staging index math: 16k x 16b sub-chunk = 64 float4
    const int h_kk0 = l >> 2,        h_q0 = l & 3;
    const int h_kk1 = (l + 32) >> 2, h_q1 = (l + 32) & 3;

    for (int t = 0; t < T_STEPS; t++) {
        const float4* hp4 = (const float4*)g_h[t & 1];   // h[k][b], row = 16 f4
        float*        hnext = g_h[(t + 1) & 1];

        unsigned long long acc[2][4];
#pragma unroll
        for (int jj = 0; jj < 2; jj++)
#pragma unroll
            for (int p = 0; p < 4; p++) acc[jj][p] = 0ull;

        // prefetch sub-chunk 0 (after grid barrier -> h_prev complete)
        float4 hreg0 = ldcg4(&hp4[(size_t)(k0w + h_kk0) * 16 + bb * 4 + h_q0]);
        float4 hreg1 = ldcg4(&hp4[(size_t)(k0w + h_kk1) * 16 + bb * 4 + h_q1]);
        // store into buf 0
        *(float4*)&hst[0 * 256 + h_kk0 * 16 + h_q0 * 4] = hreg0;
        *(float4*)&hst[0 * 256 + h_kk1 * 16 + h_q1 * 4] = hreg1;
        __syncwarp();

#pragma unroll
        for (int sc = 0; sc < 4; sc++) {
            const int buf = sc & 1;
            // prefetch next sub-chunk (overlaps with compute)
            if (sc < 3) {
                const int k0 = k0w + (sc + 1) * 16;
                hreg0 = ldcg4(&hp4[(size_t)(k0 + h_kk0) * 16 + bb * 4 + h_q0]);
                hreg1 = ldcg4(&hp4[(size_t)(k0 + h_kk1) * 16 + bb * 4 + h_q1]);
            }
            // compute 16 k: per k, 2 LDS.128 (broadcast) + 1 LDS.64 + 2 pack + 8 FFMA2
            const float* wrow = whs + (size_t)(k0w + sc * 16) * 32;
#pragma unroll
            for (int kk = 0; kk < 16; kk++) {
                ulonglong2 hv01 = *(const ulonglong2*)&hst[buf * 256 + kk * 16 + bh * 8];
                ulonglong2 hv23 = *(const ulonglong2*)&hst[buf * 256 + kk * 16 + bh * 8 + 4];
                float2 wp = *(const float2*)&wrow[kk * 32 + jp * 2];
                unsigned long long w0 = pack2(wp.x, wp.x);
                unsigned long long w1 = pack2(wp.y, wp.y);
                ffma2(acc[0][0], hv01.x, w0);
                ffma2(acc[0][1], hv01.y, w0);
                ffma2(acc[0][2], hv23.x, w0);
                ffma2(acc[0][3], hv23.y, w0);
                ffma2(acc[1][0], hv01.x, w1);
                ffma2(acc[1][1], hv01.y, w1);
                ffma2(acc[1][2], hv23.x, w1);
                ffma2(acc[1][3], hv23.y, w1);
            }
            if (sc < 3) {
                // store prefetched regs into the other buffer
                const int d = buf ^ 1;
                *(float4*)&hst[d * 256 + h_kk0 * 16 + h_q0 * 4] = hreg0;
                *(float4*)&hst[d * 256 + h_kk1 * 16 + h_q1 * 4] = hreg1;
                __syncwarp();
            }
        }

        // ---- cross-warp reduction of 16 k-partials (reuse hstage as red[16][512]) ----
        __syncthreads();
#pragma unroll
        for (int jj = 0; jj < 2; jj++) {
            int o = (jp * 2 + jj) * 16 + bh * 8;
            float2 a0 = unpack2(acc[jj][0]), a1 = unpack2(acc[jj][1]);
            float2 a2 = unpack2(acc[jj][2]), a3 = unpack2(acc[jj][3]);
            *(float4*)&hstage[w * 512 + o]     = make_float4(a0.x, a0.y, a1.x, a1.y);
            *(float4*)&hstage[w * 512 + o + 4] = make_float4(a2.x, a2.y, a3.x, a3.y);
        }
        __syncthreads();

        // each thread finalizes one output
        {
            const int o  = tid;
            const int jl = o >> 4;
            const int bl = o & 15;
            float s = 0.f;
#pragma unroll
            for (int ww = 0; ww < 16; ww++) s += hstage[ww * 512 + o];
            const int j = jb * 32 + jl;
            const int b = bb * 16 + bl;
            float p = g_P[((size_t)t * HID + j) * B_SZ + b];
            hnext[j * B_SZ + b] = tanhf(p + s);
        }

        grid_barrier();
    }
}

// ---------------- final: y[b][o] = sum_j h[j][b]*W2[j][o] + b2[o] ----------------
__global__ __launch_bounds__(128) void final_kernel(
    const float* __restrict__ W2, const float* __restrict__ b2,
    float* __restrict__ out)
{
    __shared__ float hs[128 * 16];
    __shared__ float ws[128 * 32];

    const int tid = threadIdx.x;
    const int ol = tid & 31;
    const int bt = tid >> 5;
    const int ob = blockIdx.x;
    const int bb = blockIdx.y;

    const float* hfin = g_h[T_STEPS & 1];
    const float4* hp4 = (const float4*)hfin;
    const float4* w24 = (const float4*)W2;

    unsigned long long acc0 = 0ull, acc1 = 0ull;

    for (int c = 0; c < 8; c++) {
        const int k0 = c * 128;
#pragma unroll
        for (int i = 0; i < 4; i++) {
            int idx = tid + i * 128; int row = idx >> 2, q = idx & 3;
            *(float4*)&hs[row * 16 + q * 4] = hp4[(size_t)(k0 + row) * 16 + bb * 4 + q];
        }
#pragma unroll
        for (int i = 0; i < 8; i++) {
            int idx = tid + i * 128; int row = idx >> 3, q = idx & 7;
            *(float4*)&ws[row * 32 + q * 4] = w24[(size_t)(k0 + row) * 64 + ob * 8 + q];
        }
        __syncthreads();
#pragma unroll 8
        for (int kk = 0; kk < 128; kk++) {
            ulonglong2 hv = *(const ulonglong2*)&hs[kk * 16 + bt * 4];
            float w = ws[kk * 32 + ol];
            unsigned long long wp = pack2(w, w);
            ffma2(acc0, hv.x, wp);
            ffma2(acc1, hv.y, wp);
        }
        __syncthreads();
    }

    const int o = ob * 32 + ol;
    const int b0 = bb * 16 + bt * 4;
    const float bo = b2[o];
    float2 a0 = unpack2(acc0), a1 = unpack2(acc1);
    out[(b0 + 0) * OUT_SZ + o] = a0.x + bo;
    out[(b0 + 1) * OUT_SZ + o] = a0.y + bo;
    out[(b0 + 2) * OUT_SZ + o] = a1.x + bo;
    out[(b0 + 3) * OUT_SZ + o] = a1.y + bo;
}

// ---------------- launch ----------------
extern "C" void kernel_launch(void* const* d_in, const int* in_sizes, int n_in,
                              void* d_out, int out_size)
{
    const float* x   = (const float*)d_in[0];
    const float* Wx  = (const float*)d_in[1];
    const float* Wh  = (const float*)d_in[2];
    const float* b   = (const float*)d_in[3];
    const float* W2  = (const float*)d_in[4];
    const float* b2  = (const float*)d_in[5];
    float* out = (float*)d_out;

    const int SMEM_BYTES = (32768 + 8192) * 4;   // 160 KB dynamic smem
    static bool attr_done = false;
    if (!attr_done) {
        cudaFuncSetAttribute(rnn_persistent_kernel,
                             cudaFuncAttributeMaxDynamicSharedMemorySize, SMEM_BYTES);
        attr_done = true;
    }

    precompute_kernel<<<dim3(16, T_STEPS), 256>>>(x, Wx, b);
    rnn_persistent_kernel<<<dim3(32, 4), 512, SMEM_BYTES>>>(Wh);
    final_kernel<<<dim3(8, 4), 128>>>(W2, b2, out);
}

// round 4
// speedup vs baseline: 1.7293x; 1.0508x over previous
#include <cuda_runtime.h>
#include <cuda_bf16.h>
#include <cstdint>

// Problem constants
#define T_TOTAL 512
#define T_STEPS 511     // reference output uses H[-2] = h after step index 510
#define B_SZ    64
#define D_IN    256
#define HID     1024
#define OUT_SZ  256
#define GROUP_CTAS 32   // CTAs per bb exchange group

// Scratch (static __device__ — no allocations allowed)
__device__ float g_P[(size_t)T_STEPS * HID * B_SZ];   // [t][j][b]  ~134 MB
__device__ float g_h[2][HID * B_SZ];                  // [j][b] double buffer

// per-bb-group barrier state, 128B-spaced to separate L2 lines (zero-init;
// monotone counters -> consistent across graph replays)
__device__ __align__(128) unsigned long long g_arrive[4 * 16];
__device__ __align__(128) unsigned long long g_gen[4 * 16];

// ---------------- f32x2 packed-FMA helpers (sm_103a FFMA2) ----------------
__device__ __forceinline__ unsigned long long pack2(float a, float b) {
    unsigned long long r;
    asm("mov.b64 %0, {%1, %2};" : "=l"(r) : "f"(a), "f"(b));
    return r;
}
__device__ __forceinline__ float2 unpack2(unsigned long long v) {
    float2 r;
    asm("mov.b64 {%0, %1}, %2;" : "=f"(r.x), "=f"(r.y) : "l"(v));
    return r;
}
__device__ __forceinline__ void ffma2(unsigned long long& acc,
                                      unsigned long long a,
                                      unsigned long long b) {
    asm("fma.rn.f32x2 %0, %1, %2, %0;" : "+l"(acc) : "l"(a), "l"(b));
}
// L1-bypassing vector load (cross-SM coherent at L2) for the h ring buffer
__device__ __forceinline__ float4 ldcg4(const float4* p) {
    float4 v;
    asm volatile("ld.global.cg.v4.f32 {%0,%1,%2,%3}, [%4];"
                 : "=f"(v.x), "=f"(v.y), "=f"(v.z), "=f"(v.w) : "l"(p));
    return v;
}
// acquire/release atomics for the group barrier
__device__ __forceinline__ unsigned long long atom_add_acqrel(unsigned long long* p,
                                                              unsigned long long v) {
    unsigned long long old;
    asm volatile("atom.acq_rel.gpu.global.add.u64 %0, [%1], %2;"
                 : "=l"(old) : "l"(p), "l"(v) : "memory");
    return old;
}
__device__ __forceinline__ void red_add_release(unsigned long long* p,
                                                unsigned long long v) {
    asm volatile("red.release.gpu.global.add.u64 [%0], %1;"
                 :: "l"(p), "l"(v) : "memory");
}
__device__ __forceinline__ unsigned long long ld_acquire(const unsigned long long* p) {
    unsigned long long v;
    asm volatile("ld.acquire.gpu.global.u64 %0, [%1];" : "=l"(v) : "l"(p) : "memory");
    return v;
}

__device__ __forceinline__ void group_barrier(int g) {
    __syncthreads();
    if (threadIdx.x == 0) {
        unsigned long long arr = atom_add_acqrel(&g_arrive[g * 16], 1ULL);
        unsigned long long target = arr / GROUP_CTAS + 1;
        if ((arr % GROUP_CTAS) == (GROUP_CTAS - 1)) {
            red_add_release(&g_gen[g * 16], 1ULL);
        } else {
            while (ld_acquire(&g_gen[g * 16]) < target) { }
        }
    }
    __syncthreads();
}

// ---------------- precompute: P[t][j][b] = sum_d x[t][b][d]*Wx[d][j] + bias[j] --------
// v2: x kept UNtransposed in smem (xs0[b][d], conflict-free f4 stores);
// inner loop does broadcast scalar reads (banks verified conflict-free).
__global__ __launch_bounds__(256) void precompute_kernel(
    const float* __restrict__ x, const float* __restrict__ Wx,
    const float* __restrict__ bias)
{
    __shared__ float xs0[64 * 68];  // [b][d]  stride 68
    __shared__ float ws[64 * 64];   // [d][j]

    const int t  = blockIdx.y;
    const int jb = blockIdx.x;
    const int tid = threadIdx.x;
    const int jt = tid & 15;
    const int bt = tid >> 4;

    const float4* x4  = (const float4*)x;
    const float4* Wx4 = (const float4*)Wx;

    unsigned long long acc[4][2];
#pragma unroll
    for (int jj = 0; jj < 4; jj++) { acc[jj][0] = 0ull; acc[jj][1] = 0ull; }

    for (int dt = 0; dt < 4; dt++) {
        // stage x tile natural layout: xs0[b][d] (f4 stores, conflict-free)
#pragma unroll
        for (int i = 0; i < 4; i++) {
            int idx = tid + i * 256;
            int b = idx >> 4, q = idx & 15;
            float4 v = x4[(size_t)t * 4096 + b * 64 + dt * 16 + q];
            *(float4*)&xs0[b * 68 + q * 4] = v;
        }
        // stage Wx tile : ws[d][j]
#pragma unroll
        for (int i = 0; i < 4; i++) {
            int idx = tid + i * 256;
            int row = idx >> 4, q = idx & 15;
            *(float4*)&ws[row * 64 + q * 4] =
                Wx4[(size_t)(dt * 64 + row) * 256 + jb * 16 + q];
        }
        __syncthreads();

        const float* xr = &xs0[bt * 4 * 68];
#pragma unroll 8
        for (int dd = 0; dd < 64; dd++) {
            unsigned long long xv0 = pack2(xr[dd], xr[dd + 68]);
            unsigned long long xv1 = pack2(xr[dd + 136], xr[dd + 204]);
            float4 wv = *(const float4*)&ws[dd * 64 + jt * 4];
            unsigned long long w0 = pack2(wv.x, wv.x);
            unsigned long long w1 = pack2(wv.y, wv.y);
            unsigned long long w2 = pack2(wv.z, wv.z);
            unsigned long long w3 = pack2(wv.w, wv.w);
            ffma2(acc[0][0], xv0, w0); ffma2(acc[0][1], xv1, w0);
            ffma2(acc[1][0], xv0, w1); ffma2(acc[1][1], xv1, w1);
            ffma2(acc[2][0], xv0, w2); ffma2(acc[2][1], xv1, w2);
            ffma2(acc[3][0], xv0, w3); ffma2(acc[3][1], xv1, w3);
        }
        __syncthreads();
    }

    const int b0 = bt * 4;
#pragma unroll
    for (int jj = 0; jj < 4; jj++) {
        int j = jb * 64 + jt * 4 + jj;
        float bj = bias[j];
        float2 a0 = unpack2(acc[jj][0]);
        float2 a1 = unpack2(acc[jj][1]);
        float4 o = make_float4(a0.x + bj, a0.y + bj, a1.x + bj, a1.y + bj);
        *(float4*)&g_P[((size_t)t * HID + j) * B_SZ + b0] = o;
    }
}

// ---------------- persistent recurrence kernel (v3) ----------------
// grid (32 jb, 4 bb) = 128 CTAs, 512 threads = 16 warps. All CTAs resident.
// Wh slice [1024 k][32 j] in smem for the whole kernel (128 KB).
// Per step: warp w reduces k in [w*64, w*64+64) over the 32j x 16b tile.
// h slice (64k x 16b) loaded in one shot (8x ld.cg.128, MLP=8), single
// syncwarp, straight 64-k FFMA2 loop, one-syncthreads reduction, tanh,
// per-bb-group acquire/release barrier. P[t] prefetched at step start.
__global__ __launch_bounds__(512) void rnn_persistent_kernel(const float* __restrict__ Wh)
{
    extern __shared__ float smem[];
    float* whs    = smem;            // [1024 k][32 j]        = 32768 floats (128 KB)
    float* hstage = smem + 32768;    // [16 warp][1024]       = 16384 floats (64 KB)
                                     // per warp: h slice 64k x 16b (1024 f);
                                     // first 512 f reused as reduction partials

    const int tid = threadIdx.x;
    const int w   = tid >> 5;
    const int l   = tid & 31;
    const int jp  = l & 15;            // j pair: j_local = jp*2 + {0,1}
    const int bh  = l >> 4;            // b half: b_local = bh*8 + {0..7}
    const int jb  = blockIdx.x;        // 32 blocks of 32 j
    const int bb  = blockIdx.y;        // 4 blocks of 16 b

    // ---- load Wh slice into smem once: whs[k*32 + jl] ----
    {
        const float4* wh4  = (const float4*)Wh;    // Wh[k][j], row = 256 f4
        float4*       whs4 = (float4*)whs;         // row = 8 f4
#pragma unroll
        for (int i = 0; i < 16; i++) {
            int idx = tid + i * 512;               // 8192 float4
            int k = idx >> 3, q = idx & 7;
            whs4[k * 8 + q] = wh4[(size_t)k * 256 + jb * 8 + q];
        }
    }
    // ---- zero h0 slice ----
    {
        int jl = tid >> 4, bl = tid & 15;
        g_h[0][(jb * 32 + jl) * B_SZ + bb * 16 + bl] = 0.f;
    }
    group_barrier(bb);

    const int k0w = w * 64;
    float* hst = hstage + w * 1024;

    // P slice index for this thread (o = tid -> jl = o>>4, bl = o&15)
    const float* pptr0 = &g_P[((size_t)(jb * 32 + (tid >> 4))) * B_SZ + bb * 16 + (tid & 15)];
    float* const hn_base0 = &g_h[0][(jb * 32 + (tid >> 4)) * B_SZ + bb * 16 + (tid & 15)];
    float* const hn_base1 = &g_h[1][(jb * 32 + (tid >> 4)) * B_SZ + bb * 16 + (tid & 15)];

    for (int t = 0; t < T_STEPS; t++) {
        const float4* hp4 = (const float4*)g_h[t & 1];   // h[k][b], row = 16 f4

        // early P prefetch (DRAM latency hidden under the 64-k compute)
        float pval = __ldcs(pptr0 + (size_t)t * (HID * B_SZ));

        // one-shot h slice load: 64k x 16b = 256 f4 per warp, 8 per lane
        float4 hreg[8];
#pragma unroll
        for (int i = 0; i < 8; i++) {
            int idx = l + 32 * i; int kk = idx >> 2, q = idx & 3;
            hreg[i] = ldcg4(&hp4[(size_t)(k0w + kk) * 16 + bb * 4 + q]);
        }
#pragma unroll
        for (int i = 0; i < 8; i++) {
            int idx = l + 32 * i; int kk = idx >> 2, q = idx & 3;
            *(float4*)&hst[kk * 16 + q * 4] = hreg[i];
        }
        __syncwarp();

        unsigned long long acc[2][4];
#pragma unroll
        for (int jj = 0; jj < 2; jj++)
#pragma unroll
            for (int p = 0; p < 4; p++) acc[jj][p] = 0ull;

        const float* wrow = whs + (size_t)k0w * 32;
#pragma unroll
        for (int kk = 0; kk < 64; kk++) {
            ulonglong2 hv01 = *(const ulonglong2*)&hst[kk * 16 + bh * 8];
            ulonglong2 hv23 = *(const ulonglong2*)&hst[kk * 16 + bh * 8 + 4];
            float2 wp = *(const float2*)&wrow[kk * 32 + jp * 2];
            unsigned long long w0 = pack2(wp.x, wp.x);
            unsigned long long w1 = pack2(wp.y, wp.y);
            ffma2(acc[0][0], hv01.x, w0);
            ffma2(acc[0][1], hv01.y, w0);
            ffma2(acc[0][2], hv23.x, w0);
            ffma2(acc[0][3], hv23.y, w0);
            ffma2(acc[1][0], hv01.x, w1);
            ffma2(acc[1][1], hv01.y, w1);
            ffma2(acc[1][2], hv23.x, w1);
            ffma2(acc[1][3], hv23.y, w1);
        }

        // write k-partials into own warp region (no sync needed before: own region)
#pragma unroll
        for (int jj = 0; jj < 2; jj++) {
            int o = (jp * 2 + jj) * 16 + bh * 8;
            float2 a0 = unpack2(acc[jj][0]), a1 = unpack2(acc[jj][1]);
            float2 a2 = unpack2(acc[jj][2]), a3 = unpack2(acc[jj][3]);
            *(float4*)&hst[o]     = make_float4(a0.x, a0.y, a1.x, a1.y);
            *(float4*)&hst[o + 4] = make_float4(a2.x, a2.y, a3.x, a3.y);
        }
        __syncthreads();

        // each thread finalizes one output o = tid
        {
            float s = 0.f;
#pragma unroll
            for (int ww = 0; ww < 16; ww++) s += hstage[ww * 1024 + tid];
            float* hn = ((t + 1) & 1) ? hn_base1 : hn_base0;
            *hn = tanhf(pval + s);
        }

        group_barrier(bb);
    }
}

// ---------------- final: y[b][o] = sum_j h[j][b]*W2[j][o] + b2[o] ----------------
__global__ __launch_bounds__(128) void final_kernel(
    const float* __restrict__ W2, const float* __restrict__ b2,
    float* __restrict__ out)
{
    __shared__ float hs[128 * 16];
    __shared__ float ws[128 * 32];

    const int tid = threadIdx.x;
    const int ol = tid & 31;
    const int bt = tid >> 5;
    const int ob = blockIdx.x;
    const int bb = blockIdx.y;

    const float* hfin = g_h[T_STEPS & 1];
    const float4* hp4 = (const float4*)hfin;
    const float4* w24 = (const float4*)W2;

    unsigned long long acc0 = 0ull, acc1 = 0ull;

    for (int c = 0; c < 8; c++) {
        const int k0 = c * 128;
#pragma unroll
        for (int i = 0; i < 4; i++) {
            int idx = tid + i * 128; int row = idx >> 2, q = idx & 3;
            *(float4*)&hs[row * 16 + q * 4] = hp4[(size_t)(k0 + row) * 16 + bb * 4 + q];
        }
#pragma unroll
        for (int i = 0; i < 8; i++) {
            int idx = tid + i * 128; int row = idx >> 3, q = idx & 7;
            *(float4*)&ws[row * 32 + q * 4] = w24[(size_t)(k0 + row) * 64 + ob * 8 + q];
        }
        __syncthreads();
#pragma unroll 8
        for (int kk = 0; kk < 128; kk++) {
            ulonglong2 hv = *(const ulonglong2*)&hs[kk * 16 + bt * 4];
            float w = ws[kk * 32 + ol];
            unsigned long long wp = pack2(w, w);
            ffma2(acc0, hv.x, wp);
            ffma2(acc1, hv.y, wp);
        }
        __syncthreads();
    }

    const int o = ob * 32 + ol;
    const int b0 = bb * 16 + bt * 4;
    const float bo = b2[o];
    float2 a0 = unpack2(acc0), a1 = unpack2(acc1);
    out[(b0 + 0) * OUT_SZ + o] = a0.x + bo;
    out[(b0 + 1) * OUT_SZ + o] = a0.y + bo;
    out[(b0 + 2) * OUT_SZ + o] = a1.x + bo;
    out[(b0 + 3) * OUT_SZ + o] = a1.y + bo;
}

// ---------------- launch ----------------
extern "C" void kernel_launch(void* const* d_in, const int* in_sizes, int n_in,
                              void* d_out, int out_size)
{
    const float* x   = (const float*)d_in[0];
    const float* Wx  = (const float*)d_in[1];
    const float* Wh  = (const float*)d_in[2];
    const float* b   = (const float*)d_in[3];
    const float* W2  = (const float*)d_in[4];
    const float* b2  = (const float*)d_in[5];
    float* out = (float*)d_out;

    const int SMEM_BYTES = (32768 + 16384) * 4;   // 192 KB dynamic smem
    static bool attr_done = false;
    if (!attr_done) {
        cudaFuncSetAttribute(rnn_persistent_kernel,
                             cudaFuncAttributeMaxDynamicSharedMemorySize, SMEM_BYTES);
        attr_done = true;
    }

    precompute_kernel<<<dim3(16, T_STEPS), 256>>>(x, Wx, b);
    rnn_persistent_kernel<<<dim3(32, 4), 512, SMEM_BYTES>>>(Wh);
    final_kernel<<<dim3(8, 4), 128>>>(W2, b2, out);
}